// round 11
// baseline (speedup 1.0000x reference)
#include <cuda_runtime.h>
#include <cuda_bf16.h>
#include <cstdint>

// Problem constants
#define Bsz   64
#define Lsz   64
#define Hsz   128
#define Ssz   64
#define INsz  16

// c history: [s][b][h]
__device__ float g_chist[Ssz * Bsz * Hsz];

// ---------------- helpers ----------------
__device__ __forceinline__ uint32_t smem_u32(const void* p) {
    uint32_t a;
    asm("{ .reg .u64 t; cvta.to.shared.u64 t, %1; cvt.u32.u64 %0, t; }"
        : "=r"(a) : "l"(p));
    return a;
}
__device__ __forceinline__ uint32_t mapa_rank(uint32_t laddr, uint32_t rk) {
    uint32_t ra;
    asm("mapa.shared::cluster.u32 %0, %1, %2;" : "=r"(ra) : "r"(laddr), "r"(rk));
    return ra;
}
__device__ __forceinline__ void st_cluster_b64(uint32_t addr, uint64_t v) {
    asm volatile("st.shared::cluster.b64 [%0], %1;" :: "r"(addr), "l"(v) : "memory");
}
__device__ __forceinline__ uint32_t cluster_rank() {
    uint32_t r; asm("mov.u32 %0, %%cluster_ctarank;" : "=r"(r)); return r;
}
__device__ __forceinline__ void cluster_sync() {
    asm volatile("barrier.cluster.arrive.aligned;" ::: "memory");
    asm volatile("barrier.cluster.wait.aligned;" ::: "memory");
}
__device__ __forceinline__ float sigf(float x) {
    return __fdividef(1.0f, 1.0f + __expf(-x));
}
__device__ __forceinline__ float tanh_acc(float x) {
    return __fmaf_rn(2.0f, sigf(2.0f * x), -1.0f);
}
__device__ __forceinline__ uint64_t pack2(float lo, float hi) {
    uint64_t r; asm("mov.b64 %0, {%1, %2};" : "=l"(r) : "f"(lo), "f"(hi)); return r;
}
__device__ __forceinline__ void unpack2(uint64_t v, float& lo, float& hi) {
    asm("mov.b64 {%0, %1}, %2;" : "=f"(lo), "=f"(hi) : "l"(v));
}
__device__ __forceinline__ void fma2(uint64_t& d, uint64_t a, uint64_t b) {
    asm("fma.rn.f32x2 %0, %1, %2, %0;" : "+l"(d) : "l"(a), "l"(b));
}
__device__ __forceinline__ void mbar_arrive_remote(uint32_t raddr) {
    asm volatile("mbarrier.arrive.release.cluster.shared::cluster.b64 _, [%0];"
                 :: "r"(raddr) : "memory");
}
__device__ __forceinline__ void mbar_wait(uint32_t addr, uint32_t parity) {
    uint32_t done;
    asm volatile(
        "{\n\t.reg .pred p;\n\t"
        "mbarrier.try_wait.parity.acquire.cluster.shared::cta.b64 p, [%1], %2;\n\t"
        "selp.b32 %0, 1, 0, p;\n\t}"
        : "=r"(done) : "r"(addr), "r"(parity) : "memory");
    if (!done) {
        asm volatile(
            "{\n\t.reg .pred P1;\n\t"
            "WAIT_LOOP_%=:\n\t"
            "mbarrier.try_wait.parity.acquire.cluster.shared::cta.b64 P1, [%0], %1, 0x989680;\n\t"
            "@P1 bra.uni WAIT_DONE_%=;\n\t"
            "bra.uni WAIT_LOOP_%=;\n\t"
            "WAIT_DONE_%=:\n\t}"
            :: "r"(addr), "r"(parity) : "memory");
    }
}
__device__ __forceinline__ float pick8(float a0, float a1, float a2, float a3,
                                       float a4, float a5, float a6, float a7, int k) {
    float s0 = (k & 1) ? a1 : a0;
    float s1 = (k & 1) ? a3 : a2;
    float s2 = (k & 1) ? a5 : a4;
    float s3 = (k & 1) ? a7 : a6;
    float t0 = (k & 2) ? s1 : s0;
    float t1 = (k & 2) ? s3 : s2;
    return (k & 4) ? t1 : t0;
}

// ---------------- kernel 1: recurrence (warp-autonomous) ----------------
// 128 CTAs = 32 clusters x 4. Cluster ci: batches {2ci, 2ci+1}.
// CTA rank r: h-tile [32r, 32r+32). Warp w: h = r*32 + 4w .. +4 (ALL 4 gates).
// Lane (kq=l>>2, g=l&3): gate g, k-chunk [32kq, 32kq+32), j-cols g*128 + r*32 + 4w..+4.
// k-reduce: 3x shfl.bfly (xor 4,8,16). gate-allgather: 2x shfl (xor 1,2).
// All lanes compute cn/hn redundantly; each lane sends 2 values to rank l>>3.
// NO __syncthreads in the loop; one mbarrier rendezvous per step.
extern "C" __global__ void __cluster_dims__(4, 1, 1) __launch_bounds__(256, 1)
lstm_recur_kernel(const float* __restrict__ emb,
                  const float* __restrict__ Wg,
                  const float* __restrict__ bg)
{
    __shared__ float2 inpd[2 * 2 * 256];        // [buf][b][k] dup pairs (8 KB)
    __shared__ __align__(8) uint64_t mbar;

    const int tid = threadIdx.x;
    const uint32_t r = cluster_rank();
    const int b0 = (blockIdx.x >> 2) * 2;

    const int w  = tid >> 5;          // warp: h-subrange
    const int l  = tid & 31;
    const int kq = l >> 2;            // k-chunk
    const int g  = l & 3;             // gate
    const int hb = (int)(r << 5) + w * 4;   // global h base of this warp
    const int jgbase = g * 128 + hb;        // W column base (4 consecutive cols)

    // ---- W slice to registers: wp[2kk+p] = pack2 of j-pair p at k=kq*32+kk ----
    uint64_t wp[64];
    #pragma unroll
    for (int kk = 0; kk < 32; ++kk) {
        const float4 w4 = *(const float4*)(Wg + (size_t)(kq * 32 + kk) * 512 + jgbase);
        wp[2 * kk]     = pack2(w4.x, w4.y);
        wp[2 * kk + 1] = pack2(w4.z, w4.w);
    }
    const float4 bias4 = *(const float4*)(bg + jgbase);
    const float bias_f[4] = {bias4.x, bias4.y, bias4.z, bias4.w};

    // ---- init inpd buf0 = dup([emb[:,0,:], zeros]) ----
    for (int idx = tid; idx < 512; idx += 256) {
        int b = idx >> 8, k = idx & 255;
        float v = (k < 128) ? emb[(size_t)(b0 + b) * (Lsz * Hsz) + k] : 0.0f;
        inpd[idx] = make_float2(v, v);
    }
    if (tid == 0) {
        asm volatile("mbarrier.init.shared.b64 [%0], 256;"
                     :: "r"(smem_u32(&mbar)) : "memory");
    }
    __syncthreads();
    cluster_sync();   // mbar + inpd visible cluster-wide

    // ---- send role: rank = l>>3, batch = (l>>2)&1, h-sub = l&3 ----
    const uint32_t rk = (uint32_t)(l >> 3);
    const int sb  = (l >> 2) & 1;
    const int shs = l & 3;
    const uint32_t mbar_l = smem_u32(&mbar);
    const uint32_t inpd_l = smem_u32(&inpd[0]);
    const uint32_t mbar_r = mapa_rank(mbar_l, rk);
    const uint32_t inpd_r = mapa_rank(inpd_l, rk);
    const uint32_t send_off_base = (uint32_t)(sb * 256 + hb + shs) * 8u;

    float c_old[8];
    #pragma unroll
    for (int i = 0; i < 8; ++i) c_old[i] = 0.0f;

    for (int t = 0; t < Ssz; ++t) {
        const int cur = t & 1, nxt = cur ^ 1;

        // ---- GEMM partials over own k-chunk ----
        const uint64_t* ip0 = (const uint64_t*)inpd + (cur * 2) * 256 + kq * 32;
        const uint64_t* ip1 = ip0 + 256;
        uint64_t a0 = 0, a1 = 0, a2 = 0, a3 = 0;
        #pragma unroll
        for (int kk = 0; kk < 32; ++kk) {
            uint64_t x0 = ip0[kk];
            uint64_t x1 = ip1[kk];
            fma2(a0, wp[2 * kk], x0);
            fma2(a1, wp[2 * kk + 1], x0);
            fma2(a2, wp[2 * kk], x1);
            fma2(a3, wp[2 * kk + 1], x1);
        }
        float v[8];   // [b*4 + hsub]
        unpack2(a0, v[0], v[1]);
        unpack2(a1, v[2], v[3]);
        unpack2(a2, v[4], v[5]);
        unpack2(a3, v[6], v[7]);

        // ---- k-reduction: butterfly over kq bits (lane bits 2,3,4) ----
        #pragma unroll
        for (int m = 4; m <= 16; m <<= 1) {
            #pragma unroll
            for (int i = 0; i < 8; ++i)
                v[i] += __shfl_xor_sync(0xffffffffu, v[i], m);
        }

        // ---- bias + own-gate activation ----
        float A[8];
        #pragma unroll
        for (int i = 0; i < 8; ++i) {
            float x = v[i] + bias_f[i & 3];
            A[i] = (g == 3) ? tanh_acc(x) : sigf(x);
        }

        // ---- allgather activated gates over g bits (lane bits 0,1) ----
        float E[8], Od[8];
        #pragma unroll
        for (int i = 0; i < 8; ++i) {
            float p = __shfl_xor_sync(0xffffffffu, A[i], 1);
            E[i]  = (g & 1) ? p : A[i];    // gate (g&~1)
            Od[i] = (g & 1) ? A[i] : p;    // gate (g|1)
        }
        float F[8], I[8], Og[8], C[8];
        #pragma unroll
        for (int i = 0; i < 8; ++i) {
            float pe = __shfl_xor_sync(0xffffffffu, E[i], 2);
            float po = __shfl_xor_sync(0xffffffffu, Od[i], 2);
            F[i]  = (g & 2) ? pe : E[i];
            I[i]  = (g & 2) ? po : Od[i];
            Og[i] = (g & 2) ? E[i] : pe;
            C[i]  = (g & 2) ? Od[i] : po;
        }

        // ---- combine (redundant on all lanes; bitwise identical) ----
        float cn[8], hn[8];
        #pragma unroll
        for (int i = 0; i < 8; ++i) {
            float c2 = __fmaf_rn(F[i], c_old[i], I[i] * C[i]);
            cn[i] = c2;
            c_old[i] = c2;
            hn[i] = Og[i] * tanh_acc(c2);
        }

        // ---- c history (lanes 0 and 4 write float4 each) ----
        if (l == 0)
            *(float4*)(g_chist + (size_t)(((t << 6) + b0) * 128 + hb)) =
                make_float4(cn[0], cn[1], cn[2], cn[3]);
        if (l == 4)
            *(float4*)(g_chist + (size_t)(((t << 6) + b0 + 1) * 128 + hb)) =
                make_float4(cn[4], cn[5], cn[6], cn[7]);

        // ---- scatter + rendezvous ----
        if (t < Ssz - 1) {
            const int idx = l & 7;   // = sb*4 + shs
            float cnv = pick8(cn[0], cn[1], cn[2], cn[3], cn[4], cn[5], cn[6], cn[7], idx);
            float hnv = pick8(hn[0], hn[1], hn[2], hn[3], hn[4], hn[5], hn[6], hn[7], idx);
            const uint32_t off = (uint32_t)(nxt * 512) * 8u + send_off_base;
            st_cluster_b64(inpd_r + off, pack2(cnv, cnv));
            st_cluster_b64(inpd_r + off + 128 * 8, pack2(hnv, hnv));
            mbar_arrive_remote(mbar_r);
            mbar_wait(mbar_l, (uint32_t)(t & 1));
        }
    }
}

// ---------------- kernel 2: projection + broadcast write ----------------
extern "C" __global__ void __launch_bounds__(128)
proj_kernel(const float* __restrict__ Wlin,
            const float* __restrict__ blin,
            float* __restrict__ out)
{
    __shared__ float sc[128];
    __shared__ float pred[8][16];
    __shared__ float pv[16];

    const int bs = blockIdx.x;
    const int b = bs >> 6, s = bs & 63;
    const int tid = threadIdx.x;

    sc[tid] = g_chist[((s << 6) + b) * 128 + tid];
    __syncthreads();

    const int o = tid & 15, hq = tid >> 4;
    float acc = 0.0f;
    #pragma unroll
    for (int u = 0; u < 16; ++u) {
        int h = (hq << 4) + u;
        acc = __fmaf_rn(sc[h], Wlin[h * 16 + o], acc);
    }
    pred[hq][o] = acc;
    __syncthreads();

    if (tid < 16) {
        float v = blin[tid];
        #pragma unroll
        for (int q = 0; q < 8; ++q) v += pred[q][tid];
        pv[tid] = v;
    }
    __syncthreads();

    float4* dst = (float4*)(out + 262144) + (size_t)((b << 12) + (s << 6)) * 4;
    int c0 = (tid & 3) << 2;
    float4 val = make_float4(pv[c0], pv[c0 + 1], pv[c0 + 2], pv[c0 + 3]);
    dst[tid]       = val;
    dst[tid + 128] = val;
}

// ---------------- kernel 3: trip passthrough copy ----------------
extern "C" __global__ void __launch_bounds__(256)
trip_copy_kernel(const float4* __restrict__ in, float4* __restrict__ out)
{
    int i = blockIdx.x * 256 + threadIdx.x;
    out[i] = in[i];
}

// ---------------- launch ----------------
extern "C" void kernel_launch(void* const* d_in, const int* in_sizes, int n_in,
                              void* d_out, int out_size)
{
    const float* trip = (const float*)d_in[0];
    // d_in[1] = valid_len (unused by reference)
    const float* emb  = (const float*)d_in[2];
    const float* Wg   = (const float*)d_in[3];
    const float* bg   = (const float*)d_in[4];
    const float* Wl   = (const float*)d_in[5];
    const float* bl   = (const float*)d_in[6];
    float* out = (float*)d_out;

    trip_copy_kernel<<<256, 256>>>((const float4*)trip, (float4*)out);
    lstm_recur_kernel<<<128, 256>>>(emb, Wg, bg);
    proj_kernel<<<Bsz * Ssz, 128>>>(Wl, bl, out);
}

// round 12
// speedup vs baseline: 1.3583x; 1.3583x over previous
#include <cuda_runtime.h>
#include <cuda_bf16.h>
#include <cstdint>

// Problem constants
#define Bsz   64
#define Lsz   64
#define Hsz   128
#define Ssz   64
#define INsz  16

// c history: [s][b][h]
__device__ float g_chist[Ssz * Bsz * Hsz];

// ---------------- helpers ----------------
__device__ __forceinline__ uint32_t smem_u32(const void* p) {
    uint32_t a;
    asm("{ .reg .u64 t; cvta.to.shared.u64 t, %1; cvt.u32.u64 %0, t; }"
        : "=r"(a) : "l"(p));
    return a;
}
__device__ __forceinline__ uint32_t mapa_rank(uint32_t laddr, uint32_t rk) {
    uint32_t ra;
    asm("mapa.shared::cluster.u32 %0, %1, %2;" : "=r"(ra) : "r"(laddr), "r"(rk));
    return ra;
}
__device__ __forceinline__ void st_cluster_b64(uint32_t addr, uint64_t v) {
    asm volatile("st.shared::cluster.b64 [%0], %1;" :: "r"(addr), "l"(v) : "memory");
}
__device__ __forceinline__ uint32_t cluster_rank() {
    uint32_t r; asm("mov.u32 %0, %%cluster_ctarank;" : "=r"(r)); return r;
}
__device__ __forceinline__ void cluster_sync() {
    asm volatile("barrier.cluster.arrive.aligned;" ::: "memory");
    asm volatile("barrier.cluster.wait.aligned;" ::: "memory");
}
__device__ __forceinline__ float sigf(float x) {
    return __fdividef(1.0f, 1.0f + __expf(-x));
}
__device__ __forceinline__ float tanh_acc(float x) {
    return __fmaf_rn(2.0f, sigf(2.0f * x), -1.0f);
}
__device__ __forceinline__ uint64_t pack2(float lo, float hi) {
    uint64_t r; asm("mov.b64 %0, {%1, %2};" : "=l"(r) : "f"(lo), "f"(hi)); return r;
}
__device__ __forceinline__ void unpack2(uint64_t v, float& lo, float& hi) {
    asm("mov.b64 {%0, %1}, %2;" : "=f"(lo), "=f"(hi) : "l"(v));
}
__device__ __forceinline__ void fma2(uint64_t& d, uint64_t a, uint64_t b) {
    asm("fma.rn.f32x2 %0, %1, %2, %0;" : "+l"(d) : "l"(a), "l"(b));
}
__device__ __forceinline__ void mbar_arrive_remote(uint32_t raddr) {
    asm volatile("mbarrier.arrive.release.cluster.shared::cluster.b64 _, [%0];"
                 :: "r"(raddr) : "memory");
}
__device__ __forceinline__ void mbar_wait(uint32_t addr, uint32_t parity) {
    uint32_t done;
    asm volatile(
        "{\n\t.reg .pred p;\n\t"
        "mbarrier.try_wait.parity.acquire.cluster.shared::cta.b64 p, [%1], %2;\n\t"
        "selp.b32 %0, 1, 0, p;\n\t}"
        : "=r"(done) : "r"(addr), "r"(parity) : "memory");
    if (!done) {
        asm volatile(
            "{\n\t.reg .pred P1;\n\t"
            "WAIT_LOOP_%=:\n\t"
            "mbarrier.try_wait.parity.acquire.cluster.shared::cta.b64 P1, [%0], %1, 0x989680;\n\t"
            "@P1 bra.uni WAIT_DONE_%=;\n\t"
            "bra.uni WAIT_LOOP_%=;\n\t"
            "WAIT_DONE_%=:\n\t}"
            :: "r"(addr), "r"(parity) : "memory");
    }
}
__device__ __forceinline__ float pick8(const float* v, int k) {
    float s0 = (k & 1) ? v[1] : v[0];
    float s1 = (k & 1) ? v[3] : v[2];
    float s2 = (k & 1) ? v[5] : v[4];
    float s3 = (k & 1) ? v[7] : v[6];
    float t0 = (k & 2) ? s1 : s0;
    float t1 = (k & 2) ? s3 : s2;
    return (k & 4) ? t1 : t0;
}

// ---------------- kernel 1: recurrence (warp-autonomous, lane-transposed) ----------------
// 128 CTAs = 32 clusters x 4. Cluster ci: batches {2ci, 2ci+1}.
// CTA rank r: h-tile [32r, 32r+32). Warp w: h = r*32 + 4w..+4 (all 4 gates).
// GEMM role: lane l = (kq<<2)|g, gate g, k-chunk [32kq,+32).
// After 3-round k-butterfly (xor 4,8,16), lane has v[8] (el = b*4+hsub) for gate g.
// TRANSPOSE: w_sel = v[kq] (FSEL tree); one shfl from src ((l&7)<<2)|(l>>3)
//   gives lane x the scalar for gate x>>3 of element x&7 -> scalar activation,
//   3-shfl gate gather, scalar combine. No arrays live past the butterfly.
// Scatter: lane l sends element l&7 to rank l>>3 (same mapping as validated R11).
// NO __syncthreads in loop; one mbarrier rendezvous (256 arrivals) per step.
extern "C" __global__ void __cluster_dims__(4, 1, 1) __launch_bounds__(256, 1)
lstm_recur_kernel(const float* __restrict__ emb,
                  const float* __restrict__ Wg,
                  const float* __restrict__ bg)
{
    __shared__ float2 inpd[2 * 2 * 256];        // [buf][b][k] dup pairs (8 KB)
    __shared__ __align__(8) uint64_t mbar;

    const int tid = threadIdx.x;
    const uint32_t r = cluster_rank();
    const int b0 = (blockIdx.x >> 2) * 2;

    const int w  = tid >> 5;                // warp: h-quad
    const int l  = tid & 31;
    const int kq = l >> 2;                  // GEMM k-chunk
    const int g  = l & 3;                   // GEMM gate
    const int hb = (int)(r << 5) + w * 4;   // global h base of this warp
    const int jgbase = g * 128 + hb;        // W column base (4 consecutive cols)

    // ---- W slice to registers: j-pairs packed for fma.rn.f32x2 ----
    uint64_t wp[64];
    #pragma unroll
    for (int kk = 0; kk < 32; ++kk) {
        const float4 w4 = *(const float4*)(Wg + (size_t)(kq * 32 + kk) * 512 + jgbase);
        wp[2 * kk]     = pack2(w4.x, w4.y);
        wp[2 * kk + 1] = pack2(w4.z, w4.w);
    }
    // bias for TRANSPOSED role: gate l>>3, column h = hb + (l&3)
    const float bias_u = bg[(l >> 3) * 128 + hb + (l & 3)];

    // ---- init inpd buf0 = dup([emb[:,0,:], zeros]) ----
    for (int idx = tid; idx < 512; idx += 256) {
        int b = idx >> 8, k = idx & 255;
        float v0 = (k < 128) ? emb[(size_t)(b0 + b) * (Lsz * Hsz) + k] : 0.0f;
        inpd[idx] = make_float2(v0, v0);
    }
    if (tid == 0) {
        asm volatile("mbarrier.init.shared.b64 [%0], 256;"
                     :: "r"(smem_u32(&mbar)) : "memory");
    }
    __syncthreads();
    cluster_sync();   // mbar + inpd visible cluster-wide

    // ---- send role: element el = l&7 -> rank l>>3; b = (l>>2)&1, hsub = l&3 ----
    const uint32_t rk = (uint32_t)(l >> 3);
    const uint32_t mbar_l = smem_u32(&mbar);
    const uint32_t inpd_l = smem_u32(&inpd[0]);
    const uint32_t mbar_r = mapa_rank(mbar_l, rk);
    const uint32_t inpd_r = mapa_rank(inpd_l, rk);
    const uint32_t send_off_base = (uint32_t)(((l >> 2) & 1) * 256 + hb + (l & 3)) * 8u;

    float c_old = 0.0f;   // c of element l&7 (replicated across gate groups)

    for (int t = 0; t < Ssz; ++t) {
        const int cur = t & 1, nxt = cur ^ 1;

        // ---- GEMM partials over own k-chunk (validated FFMA2 form) ----
        const uint64_t* ip0 = (const uint64_t*)inpd + (cur * 2) * 256 + kq * 32;
        const uint64_t* ip1 = ip0 + 256;
        uint64_t a0 = 0, a1 = 0, a2 = 0, a3 = 0;
        #pragma unroll
        for (int kk = 0; kk < 32; ++kk) {
            uint64_t x0 = ip0[kk];
            uint64_t x1 = ip1[kk];
            fma2(a0, wp[2 * kk], x0);
            fma2(a1, wp[2 * kk + 1], x0);
            fma2(a2, wp[2 * kk], x1);
            fma2(a3, wp[2 * kk + 1], x1);
        }
        float v[8];   // [b*4 + hsub], this lane's gate g
        unpack2(a0, v[0], v[1]);
        unpack2(a1, v[2], v[3]);
        unpack2(a2, v[4], v[5]);
        unpack2(a3, v[6], v[7]);

        // ---- k-reduction: butterfly over kq bits (lane bits 2,3,4) ----
        #pragma unroll
        for (int m = 4; m <= 16; m <<= 1) {
            #pragma unroll
            for (int i = 0; i < 8; ++i)
                v[i] += __shfl_xor_sync(0xffffffffu, v[i], m);
        }

        // ---- transpose: lane x <- gate x>>3 of element x&7 ----
        float w_sel = pick8(v, kq);
        float u = __shfl_sync(0xffffffffu, w_sel, ((l & 7) << 2) | (l >> 3));
        u += bias_u;
        // activation by transposed gate role (gate 3 = candidate -> tanh)
        float A = (l >= 24) ? tanh_acc(u) : sigf(u);

        // ---- gate gather over lane bits 3,4 ----
        float t1 = __shfl_xor_sync(0xffffffffu, A, 8);
        float sFO = (l & 8) ? t1 : A;    // F (bit4=0) or O (bit4=1)
        float sIC = (l & 8) ? A : t1;    // I or C
        float t2 = __shfl_xor_sync(0xffffffffu, sFO, 16);
        float t3 = __shfl_xor_sync(0xffffffffu, sIC, 16);
        float F = (l & 16) ? t2 : sFO;
        float O = (l & 16) ? sFO : t2;
        float I = (l & 16) ? t3 : sIC;
        float C = (l & 16) ? sIC : t3;

        // ---- combine: scalar per lane (element l&7); identical across gate groups ----
        float cn = __fmaf_rn(F, c_old, I * C);
        float hn = O * tanh_acc(cn);
        c_old = cn;

        // ---- c history: lanes 0-7 write their element's scalar ----
        if (l < 8)
            g_chist[(size_t)((t << 6) + b0 + (l >> 2)) * 128 + hb + (l & 3)] = cn;

        // ---- scatter + rendezvous (1 lane = 1 (rank, element) pair) ----
        if (t < Ssz - 1) {
            const uint32_t off = (uint32_t)(nxt * 512) * 8u + send_off_base;
            st_cluster_b64(inpd_r + off, pack2(cn, cn));
            st_cluster_b64(inpd_r + off + 128 * 8, pack2(hn, hn));
            mbar_arrive_remote(mbar_r);
            mbar_wait(mbar_l, (uint32_t)(t & 1));
        }
    }
}

// ---------------- kernel 2: projection + broadcast write ----------------
extern "C" __global__ void __launch_bounds__(128)
proj_kernel(const float* __restrict__ Wlin,
            const float* __restrict__ blin,
            float* __restrict__ out)
{
    __shared__ float sc[128];
    __shared__ float pred[8][16];
    __shared__ float pv[16];

    const int bs = blockIdx.x;
    const int b = bs >> 6, s = bs & 63;
    const int tid = threadIdx.x;

    sc[tid] = g_chist[((s << 6) + b) * 128 + tid];
    __syncthreads();

    const int o = tid & 15, hq = tid >> 4;
    float acc = 0.0f;
    #pragma unroll
    for (int u = 0; u < 16; ++u) {
        int h = (hq << 4) + u;
        acc = __fmaf_rn(sc[h], Wlin[h * 16 + o], acc);
    }
    pred[hq][o] = acc;
    __syncthreads();

    if (tid < 16) {
        float v = blin[tid];
        #pragma unroll
        for (int q = 0; q < 8; ++q) v += pred[q][tid];
        pv[tid] = v;
    }
    __syncthreads();

    float4* dst = (float4*)(out + 262144) + (size_t)((b << 12) + (s << 6)) * 4;
    int c0 = (tid & 3) << 2;
    float4 val = make_float4(pv[c0], pv[c0 + 1], pv[c0 + 2], pv[c0 + 3]);
    dst[tid]       = val;
    dst[tid + 128] = val;
}

// ---------------- kernel 3: trip passthrough copy ----------------
extern "C" __global__ void __launch_bounds__(256)
trip_copy_kernel(const float4* __restrict__ in, float4* __restrict__ out)
{
    int i = blockIdx.x * 256 + threadIdx.x;
    out[i] = in[i];
}

// ---------------- launch ----------------
extern "C" void kernel_launch(void* const* d_in, const int* in_sizes, int n_in,
                              void* d_out, int out_size)
{
    const float* trip = (const float*)d_in[0];
    // d_in[1] = valid_len (unused by reference)
    const float* emb  = (const float*)d_in[2];
    const float* Wg   = (const float*)d_in[3];
    const float* bg   = (const float*)d_in[4];
    const float* Wl   = (const float*)d_in[5];
    const float* bl   = (const float*)d_in[6];
    float* out = (float*)d_out;

    trip_copy_kernel<<<256, 256>>>((const float4*)trip, (float4*)out);
    lstm_recur_kernel<<<128, 256>>>(emb, Wg, bg);
    proj_kernel<<<Bsz * Ssz, 128>>>(Wl, bl, out);
}